// round 10
// baseline (speedup 1.0000x reference)
#include <cuda_runtime.h>
#include <math.h>
#include <stdint.h>

// ---------------- problem constants ----------------
#define BB    4
#define CCH   7
#define HWN   (512*1024)         // 524288
#define NID   7                  // ids 1..7
#define NPAIR (BB*NID)           // 28
#define NBINS 8192               // bins over error in [0,2]
#define BINW  (2.0f/8192.0f)
#define NSLICE 16
#define PXS   (HWN/NSLICE)       // 32768 pixels per k2 block
#define K1_ITERS 4               // 4 iters x 4 px = 16 px/thread

// ---------------- scratch (static __device__, zero-initialized at load; every
// run leaves all accumulators re-zeroed, so no zeroing kernel is needed) ------
__device__ __align__(16) float    g_emb[BB*HWN*2];                 // interleaved (ex,ey)
__device__ __align__(8)  float    g_seed[BB*HWN];
__device__ __align__(16) unsigned g_part[(size_t)NPAIR*NSLICE*NBINS]; // packed u16 neg|pos, fully overwritten by k2
__device__ unsigned g_pcnt[NPAIR*NSLICE];            // per-(pair,slice) positive count, overwritten by k2
__device__ float    g_stats[NPAIR*6];                // cnt, sw, sh, sp2, sp3, ssq; zeroed by k1-last
__device__ float4   g_par[NPAIR];                    // cx, cy, -log2e*exp(10 s0m), -log2e*exp(10 s1m)
__device__ float    g_var[NPAIR];
__device__ float    g_pres[NPAIR];
__device__ float    g_instl[NPAIR];                  // written by k3
__device__ float    g_sfg[NPAIR];                    // accumulated by k2, zeroed by k3-last
__device__ float    g_cls[BB*2];                     // accumulated by k1, zeroed by k3-last
__device__ float    g_sbg[BB];                       // accumulated by k1, zeroed by k3-last
__device__ unsigned g_sync1;                         // k1 last-block counter (self-resetting)
__device__ unsigned g_sync3;                         // k3 last-block counter (self-resetting)

__device__ __forceinline__ float tanh_ap(float x) {
    float y; asm("tanh.approx.f32 %0, %1;" : "=f"(y) : "f"(x)); return y;
}

// ---------------- K1: maps + moments + focal/seed_bg; register-accumulated stats ----
// 16 pixels per thread. No per-pixel warp collectives: per-id stats live in
// predicated register accumulators, flushed once per thread via smem atomics.
__global__ void __launch_bounds__(256) k1_maps(const float* __restrict__ pred,
                                               const int*   __restrict__ inst,
                                               const int*   __restrict__ lab) {
    int b   = blockIdx.y;
    int tid = threadIdx.x;
    int lane = tid & 31;

    __shared__ float s_stats[NID*6];               // cnt, sw, sh, sp2, sp3, ssq
    __shared__ float s_cls[3];                     // focal, count, seed_bg
    if (tid < NID*6) s_stats[tid] = 0.0f;
    if (tid < 3)     s_cls[tid]   = 0.0f;
    __syncthreads();

    // register accumulators per id
    float acc_p2[NID], acc_p3[NID], acc_sq[NID];
    unsigned acc_wh[NID];                          // w[0:14) | h[14:27) | cnt[27:32)
    #pragma unroll
    for (int i = 0; i < NID; i++) { acc_p2[i]=0.f; acc_p3[i]=0.f; acc_sq[i]=0.f; acc_wh[i]=0u; }
    float fv = 0.0f, sb = 0.0f;
    int   vcnt = 0;

    const float* pb = pred + (size_t)b*CCH*HWN;
    int blockPix = blockIdx.x * (256*K1_ITERS*4);

    #pragma unroll
    for (int k = 0; k < K1_ITERS; k++) {
        int p4 = blockPix + (k*256 + tid)*4;       // 4 consecutive pixels
        int g4 = p4 >> 2;
        int h  = p4 >> 10;
        int w0 = p4 & 1023;

        float4 c0 = ((const float4*)(pb + (size_t)0*HWN))[g4];
        float4 c1 = ((const float4*)(pb + (size_t)1*HWN))[g4];
        float4 c2 = ((const float4*)(pb + (size_t)2*HWN))[g4];
        float4 c3 = ((const float4*)(pb + (size_t)3*HWN))[g4];
        float4 c4 = ((const float4*)(pb + (size_t)4*HWN))[g4];
        float4 c5 = ((const float4*)(pb + (size_t)5*HWN))[g4];
        float4 c6 = ((const float4*)(pb + (size_t)6*HWN))[g4];
        size_t gi = (size_t)b*HWN + p4;
        int4 ii = ((const int4*)inst)[gi >> 2];
        int4 LL = ((const int4*)lab)[gi >> 2];

        float xm0 = (float)w0 * (2.0f/2047.0f);
        float ym  = (float)h  * (1.0f/1023.0f);
        const float DX = 2.0f/2047.0f;

        float ex0 = tanh_ap(c0.x) + xm0;
        float ex1 = tanh_ap(c0.y) + xm0 + DX;
        float ex2 = tanh_ap(c0.z) + xm0 + 2.0f*DX;
        float ex3 = tanh_ap(c0.w) + xm0 + 3.0f*DX;
        float ey0 = tanh_ap(c1.x) + ym;
        float ey1 = tanh_ap(c1.y) + ym;
        float ey2 = tanh_ap(c1.z) + ym;
        float ey3 = tanh_ap(c1.w) + ym;
        float sd0 = fmaf(0.5f, tanh_ap(0.5f*c4.x), 0.5f);
        float sd1 = fmaf(0.5f, tanh_ap(0.5f*c4.y), 0.5f);
        float sd2 = fmaf(0.5f, tanh_ap(0.5f*c4.z), 0.5f);
        float sd3 = fmaf(0.5f, tanh_ap(0.5f*c4.w), 0.5f);

        size_t e4 = (size_t)b*(HWN/2) + (p4 >> 1);
        ((float4*)g_emb)[e4]   = make_float4(ex0, ey0, ex1, ey1);
        ((float4*)g_emb)[e4+1] = make_float4(ex2, ey2, ex3, ey3);
        ((float4*)g_seed)[gi >> 2] = make_float4(sd0, sd1, sd2, sd3);

        // focal + seed_bg (register accumulation)
        int Ls[4] = {LL.x, LL.y, LL.z, LL.w};
        float p5s[4] = {c5.x, c5.y, c5.z, c5.w};
        float p6s[4] = {c6.x, c6.y, c6.z, c6.w};
        float sds[4] = {sd0, sd1, sd2, sd3};
        #pragma unroll
        for (int x = 0; x < 4; x++) {
            int L = Ls[x];
            if (L < 2) {
                float xt = (L == 0) ? p5s[x] : p6s[x];
                float xo = (L == 0) ? p6s[x] : p5s[x];
                float ez = __expf(xo - xt);
                float om = ez / (1.0f + ez);
                fv += om*om*__logf(1.0f + ez);
                vcnt++;
            }
            if (L == 0) sb += sds[x]*sds[x];
        }

        // per-id stats (predicated register accumulation)
        int ids[4] = {ii.x, ii.y, ii.z, ii.w};
        float p2s[4] = {c2.x, c2.y, c2.z, c2.w};
        float p3s[4] = {c3.x, c3.y, c3.z, c3.w};
        #pragma unroll
        for (int x = 0; x < 4; x++) {
            int id = ids[x];
            float p2 = p2s[x], p3 = p3s[x];
            float sq = fmaf(p2, p2, p3*p3);
            unsigned whc = (unsigned)(w0+x) | ((unsigned)h << 14) | (1u << 27);
            #pragma unroll
            for (int i = 0; i < NID; i++) {
                if (id == i+1) {
                    acc_wh[i] += whc;
                    acc_p2[i] += p2;
                    acc_p3[i] += p3;
                    acc_sq[i] += sq;
                }
            }
        }
    }

    // ---- flush per-thread stats to smem (once) ----
    #pragma unroll
    for (int i = 0; i < NID; i++) {
        unsigned wh = acc_wh[i];
        if (wh) {
            float* s = &s_stats[i*6];
            atomicAdd(s+0, (float)(wh >> 27));
            atomicAdd(s+1, (float)(wh & 0x3fffu));
            atomicAdd(s+2, (float)((wh >> 14) & 0x1fffu));
            atomicAdd(s+3, acc_p2[i]);
            atomicAdd(s+4, acc_p3[i]);
            atomicAdd(s+5, acc_sq[i]);
        }
    }
    // focal/seed_bg: one warp reduce per thread lifetime
    float fvv = fv, sbb = sb;
    #pragma unroll
    for (int off = 16; off > 0; off >>= 1) {
        fvv += __shfl_xor_sync(0xffffffffu, fvv, off);
        sbb += __shfl_xor_sync(0xffffffffu, sbb, off);
    }
    int vc = __reduce_add_sync(0xffffffffu, vcnt);
    if (lane == 0) {
        atomicAdd(&s_cls[0], fvv);
        atomicAdd(&s_cls[1], (float)vc);
        atomicAdd(&s_cls[2], sbb);
    }
    __syncthreads();

    if (tid < NID*6) atomicAdd(&g_stats[b*NID*6 + tid], s_stats[tid]);
    if (tid == 0) atomicAdd(&g_cls[b*2+0], s_cls[0]);
    if (tid == 1) atomicAdd(&g_cls[b*2+1], s_cls[1]);
    if (tid == 2) atomicAdd(&g_sbg[b],     s_cls[2]);
    __syncthreads();

    // ---- last-block: derive per-(b,id) params, then re-zero g_stats + counter ----
    __shared__ bool s_last;
    if (tid == 0) {
        __threadfence();
        unsigned nb = gridDim.x * gridDim.y;
        s_last = (atomicAdd(&g_sync1, 1u) == nb - 1u);
    }
    __syncthreads();
    if (s_last) {
        if (tid < NPAIR) {
            float cnt = __ldcg(&g_stats[tid*6+0]);
            float sw  = __ldcg(&g_stats[tid*6+1]);
            float shh = __ldcg(&g_stats[tid*6+2]);
            float sp2 = __ldcg(&g_stats[tid*6+3]);
            float sp3 = __ldcg(&g_stats[tid*6+4]);
            float ssq = __ldcg(&g_stats[tid*6+5]);
            float cntf = fmaxf(cnt, 1.0f);
            float cx = sw  * (2.0f/2047.0f) / cntf;
            float cy = shh * (1.0f/1023.0f) / cntf;
            float sm0 = sp2/cntf, sm1 = sp3/cntf;
            float var = (ssq - 2.0f*sm0*sp2 + sm0*sm0*cnt
                             - 2.0f*sm1*sp3 + sm1*sm1*cnt) / (2.0f*cntf);
            const float L2E = 1.4426950408889634f;
            g_par[tid]  = make_float4(cx, cy, -L2E*expf(10.0f*sm0), -L2E*expf(10.0f*sm1));
            g_var[tid]  = var;
            g_pres[tid] = (cnt > 0.0f) ? 1.0f : 0.0f;
            #pragma unroll
            for (int k = 0; k < 6; k++) g_stats[tid*6+k] = 0.0f;   // re-zero for next run
        }
        if (tid == 0) g_sync1 = 0u;
    }
}

// ---------------- K2: one (b,id,slice) per block, private smem histogram ----------------
// bin_f = 2^(13 - q*log2e) = 8192*exp(-q); neg bin = floor(bin_f), pos bin = floor(8192-bin_f).
// Packed counters: neg low 16 bits, pos high 16 bits (<=32768 px/block, no overflow).
__global__ void __launch_bounds__(512) k2_main(const int* __restrict__ inst) {
    int blk = blockIdx.x;
    int pr  = blk >> 4;
    int s   = blk & 15;
    int b   = pr / NID;
    int idv = (pr % NID) + 1;
    int tid = threadIdx.x;

    __shared__ unsigned sh[NBINS];                 // 32KB
    #pragma unroll
    for (int j = tid; j < NBINS; j += 512) sh[j] = 0u;
    __syncthreads();

    float4 par = __ldg(&g_par[pr]);
    const float4* emb4 = (const float4*)g_emb;     // 2 pixels per element
    const float2* sd2  = (const float2*)g_seed;
    const int2*   in2  = (const int2*)inst;
    size_t base = (size_t)b*(HWN/2) + (size_t)s*(PXS/2);

    float sfg = 0.0f;
    int   pcnt = 0;
    #pragma unroll 4
    for (int k = 0; k < PXS/2/512; k++) {          // 32 iterations
        size_t ti = base + (size_t)k*512 + tid;
        float4 e01  = emb4[ti];
        float2 sd01 = sd2[ti];
        int2   id01 = in2[ti];
        // pixel 0
        {
            float dx = e01.x - par.x, dy = e01.y - par.y;
            float u = fmaf(dy*dy, par.w, fmaf(dx*dx, par.z, 13.0f));
            float bf; asm("ex2.approx.f32 %0, %1;" : "=f"(bf) : "f"(u));
            bool pos = (id01.x == idv);
            if (pos) { float d = bf*(1.0f/8192.0f); float df = sd01.x - d; sfg += df*df; pcnt++; }
            float fb = pos ? (8192.0f - bf) : bf;
            int bin = min((int)fb, NBINS-1);
            atomicAdd(&sh[bin], pos ? 0x10000u : 1u);
        }
        // pixel 1
        {
            float dx = e01.z - par.x, dy = e01.w - par.y;
            float u = fmaf(dy*dy, par.w, fmaf(dx*dx, par.z, 13.0f));
            float bf; asm("ex2.approx.f32 %0, %1;" : "=f"(bf) : "f"(u));
            bool pos = (id01.y == idv);
            if (pos) { float d = bf*(1.0f/8192.0f); float df = sd01.y - d; sfg += df*df; pcnt++; }
            float fb = pos ? (8192.0f - bf) : bf;
            int bin = min((int)fb, NBINS-1);
            atomicAdd(&sh[bin], pos ? 0x10000u : 1u);
        }
    }
    __syncthreads();

    // stream smem histogram to its private partial slab (plain stores, full overwrite)
    uint4* dst = (uint4*)&g_part[(size_t)blk*NBINS];
    const uint4* src = (const uint4*)sh;
    for (int j = tid; j < NBINS/4; j += 512) dst[j] = src[j];

    // seed_fg + positive-count block reduction
    #pragma unroll
    for (int off = 16; off > 0; off >>= 1) {
        sfg  += __shfl_xor_sync(0xffffffffu, sfg, off);
        pcnt += __shfl_xor_sync(0xffffffffu, pcnt, off);
    }
    __shared__ float    swr[16];
    __shared__ unsigned swc[16];
    if ((tid & 31) == 0) { swr[tid >> 5] = sfg; swc[tid >> 5] = (unsigned)pcnt; }
    __syncthreads();
    if (tid == 0) {
        float t = 0.0f; unsigned c = 0u;
        #pragma unroll
        for (int wgo = 0; wgo < 16; wgo++) { t += swr[wgo]; c += swc[wgo]; }
        atomicAdd(&g_sfg[pr], t);
        g_pcnt[blk] = c;
    }
}

// ---------------- K3: slice-sum + descending scan + closed-form Lovasz; last block combines ----
__global__ void __launch_bounds__(1024) k3_lovasz(float* __restrict__ out) {
    int pr = blockIdx.x;
    int tid = threadIdx.x;
    int lane = tid & 31, wid = tid >> 5;

    const unsigned* part = &g_part[(size_t)pr*NSLICE*NBINS];

    // total positives from k2's per-slice counts
    __shared__ unsigned s_P;
    if (tid < 32) {
        unsigned v = (tid < NSLICE) ? g_pcnt[pr*NSLICE + tid] : 0u;
        #pragma unroll
        for (int off = 16; off > 0; off >>= 1)
            v += __shfl_xor_sync(0xffffffffu, v, off);
        if (tid == 0) s_P = v;
    }
    __shared__ unsigned s_scanN[32], s_scanP[32];
    __shared__ unsigned s_run[2];
    if (tid == 0) { s_run[0] = 0u; s_run[1] = 0u; }
    __syncthreads();
    unsigned P = s_P;

    float acc = 0.0f;
    for (int c = 0; c < NBINS/2048; c++) {         // 4 chunks, descending bins
        int lo = NBINS-2 - c*2048 - 2*tid;         // hi = lo+1
        int hi = lo + 1;
        unsigned Nlo=0, Plo=0, Nhi=0, Phi=0;
        #pragma unroll
        for (int s2 = 0; s2 < NSLICE; s2++) {
            uint2 v = *(const uint2*)&part[(size_t)s2*NBINS + lo];
            Nlo += v.x & 0xffffu; Plo += v.x >> 16;
            Nhi += v.y & 0xffffu; Phi += v.y >> 16;
        }
        unsigned tN = Nlo + Nhi, tP = Plo + Phi;
        unsigned iN = tN, iP = tP;
        #pragma unroll
        for (int off = 1; off < 32; off <<= 1) {
            unsigned an = __shfl_up_sync(0xffffffffu, iN, off);
            unsigned ap = __shfl_up_sync(0xffffffffu, iP, off);
            if (lane >= off) { iN += an; iP += ap; }
        }
        if (lane == 31) { s_scanN[wid] = iN; s_scanP[wid] = iP; }
        __syncthreads();
        unsigned bN = s_run[0], bP = s_run[1];
        for (int k = 0; k < wid; k++) { bN += s_scanN[k]; bP += s_scanP[k]; }
        unsigned n0 = bN + iN - tN;                // strictly higher error
        unsigned p0 = bP + iP - tP;

        if (P) {
            unsigned Ng = Nhi, Pg = Phi;           // hi bin first (higher error)
            if (Ng | Pg) {
                float e  = ((float)hi + 0.5f) * BINW;
                float d0 = (float)(P + n0);
                if (Pg) acc += e * (float)Pg * __fdividef(1.0f, d0);
                if (Ng) acc += e * (float)(P - p0 - Pg) * (float)Ng
                                 * __fdividef(1.0f, d0 * (d0 + (float)Ng));
                n0 += Ng; p0 += Pg;
            }
            Ng = Nlo; Pg = Plo;
            if (Ng | Pg) {
                float e  = ((float)lo + 0.5f) * BINW;
                float d0 = (float)(P + n0);
                if (Pg) acc += e * (float)Pg * __fdividef(1.0f, d0);
                if (Ng) acc += e * (float)(P - p0 - Pg) * (float)Ng
                                 * __fdividef(1.0f, d0 * (d0 + (float)Ng));
            }
        }
        __syncthreads();
        if (tid == 1023) { s_run[0] = bN + iN; s_run[1] = bP + iP; }
        __syncthreads();
    }

    #pragma unroll
    for (int off = 16; off > 0; off >>= 1)
        acc += __shfl_down_sync(0xffffffffu, acc, off);
    __shared__ float s_f[32];
    if (lane == 0) s_f[wid] = acc;
    __syncthreads();
    if (tid == 0) {
        float tot = 0.0f;
        #pragma unroll
        for (int k = 0; k < 32; k++) tot += s_f[k];
        g_instl[pr] = tot;
    }
    __syncthreads();

    // ---- last-block: final combine, then re-zero accumulators ----
    __shared__ bool s_last;
    if (tid == 0) {
        __threadfence();
        s_last = (atomicAdd(&g_sync3, 1u) == NPAIR - 1u);
    }
    __syncthreads();
    if (s_last) {
        if (tid < 32) {
            float tot = 0.0f;
            if (tid < BB) {
                float presSum = 0.0f, instS = 0.0f, varS = 0.0f, sfgS = 0.0f;
                #pragma unroll
                for (int i = 0; i < NID; i++) {
                    int q = tid*NID + i;
                    float pres = __ldcg(&g_pres[q]);
                    presSum += pres;
                    instS   += __ldcg(&g_instl[q]) * pres;
                    varS    += __ldcg(&g_var[q])   * pres;
                    sfgS    += 200.0f * __ldcg(&g_sfg[q]) * pres;
                }
                float obj  = fmaxf(presSum, 1.0f);
                float seed = (__ldcg(&g_sbg[tid]) + sfgS) * (1.0f/(float)HWN);
                float lb   = instS/obj + 10.0f*(varS/obj) + seed;
                float cls  = __ldcg(&g_cls[tid*2+0]) / fmaxf(__ldcg(&g_cls[tid*2+1]), 1.0f);
                tot = lb + cls;
            }
            #pragma unroll
            for (int off = 2; off > 0; off >>= 1)
                tot += __shfl_xor_sync(0xffffffffu, tot, off);
            if (tid == 0) out[0] = tot * 0.25f;
        }
        __syncthreads();
        // re-zero accumulators for the next replay
        if (tid < NPAIR) g_sfg[tid] = 0.0f;
        if (tid < BB*2)  g_cls[tid] = 0.0f;
        if (tid < BB)    g_sbg[tid] = 0.0f;
        if (tid == 0)    g_sync3 = 0u;
    }
}

// ---------------- launcher ----------------
extern "C" void kernel_launch(void* const* d_in, const int* in_sizes, int n_in,
                              void* d_out, int out_size) {
    const float* pred = (const float*)d_in[0];
    const int*   inst = (const int*)d_in[1];
    const int*   lab  = (const int*)d_in[2];
    float* out = (float*)d_out;

    k1_maps<<<dim3(HWN/(256*K1_ITERS*4), BB), 256>>>(pred, inst, lab);
    k2_main<<<NPAIR*NSLICE, 512>>>(inst);
    k3_lovasz<<<NPAIR, 1024>>>(out);
}